// round 15
// baseline (speedup 1.0000x reference)
#include <cuda_runtime.h>
#include <math.h>

#define BB 8
#define NN 4096
#define DD 64
#define SS 1024
#define KK 32
#define PP (BB*SS*KK)

typedef unsigned long long u64;
#define PACK2(out, lo, hi) asm("mov.b64 %0, {%1, %2};" : "=l"(out) : "r"(lo), "r"(hi))
#define UNPACK2(lo, hi, in) asm("mov.b64 {%0, %1}, %2;" : "=r"(lo), "=r"(hi) : "l"(in))
#define MUL2(out, a, b) asm("mul.rn.f32x2 %0, %1, %2;" : "=l"(out) : "l"(a), "l"(b))
#define ADD2(out, a, b) asm("add.rn.f32x2 %0, %1, %2;" : "=l"(out) : "l"(a), "l"(b))
#define FMA2(out, a, b, c) asm("fma.rn.f32x2 %0, %1, %2, %3;" : "=l"(out) : "l"(a), "l"(b), "l"(c))

static __device__ float4 g_xyzT[BB*NN];
static __device__ float  g_featT[BB*NN*DD];
static __device__ float4 g_newxyz[BB*SS];
static __device__ int    g_fps[BB*SS];
static __device__ int    g_knn[BB*SS*KK];
static __device__ double g_accStd[BB*16*2];
static __device__ double g_accBN[2*32*64*2];
static __device__ float  g_invstd[BB];
static __device__ float  g_scale[2*64];
static __device__ float  g_shift[2*64];
static __device__ float  g_t1[(size_t)PP*DD];
static __device__ float  g_t2[(size_t)PP*DD];

__global__ void k_txyz(const float* __restrict__ xyz) {
    int tid = threadIdx.x;
    int t = blockIdx.x * 256 + tid;
    if (blockIdx.x == 0) {
        for (int i = tid; i < BB*16*2; i += 256) g_accStd[i] = 0.0;
        for (int i = tid; i < 2*32*64*2; i += 256) g_accBN[i] = 0.0;
    }
    int b = t >> 12, n = t & (NN-1);
    const float* p = xyz + b * 3 * NN;
    g_xyzT[t] = make_float4(p[n], p[NN+n], p[2*NN+n], 0.f);
}

__global__ void k_tfeat(const float* __restrict__ f) {
    __shared__ float tile[32][33];
    int b = blockIdx.z, c0 = blockIdx.y * 32, n0 = blockIdx.x * 32;
    int tx = threadIdx.x, ty = threadIdx.y;
    #pragma unroll
    for (int i = 0; i < 32; i += 8)
        tile[ty+i][tx] = f[(b*DD + c0+ty+i) * NN + n0 + tx];
    __syncthreads();
    #pragma unroll
    for (int i = 0; i < 32; i += 8)
        g_featT[(size_t)(b*NN + n0+ty+i) * DD + c0 + tx] = tile[tx][ty+i];
}

// -------- FPS: 512 threads, packed f32x2, single barrier per iter (unchanged)
__global__ __launch_bounds__(512) void k_fps(float* __restrict__ out) {
    extern __shared__ float sm[];
    float* xs = sm; float* ys = sm + NN; float* zs = sm + 2*NN;
    __shared__ unsigned rv[2][16]; __shared__ int ri[2][16];
    int b = blockIdx.x, tid = threadIdx.x;
    int lane = tid & 31, w = tid >> 5;
    u64 px2[4], py2[4], pz2[4];
    float dist[8];
    #pragma unroll
    for (int i = 0; i < 4; i++) {
        int n0 = tid + 512*(2*i), n1 = n0 + 512;
        float4 v0 = g_xyzT[b*NN + n0];
        float4 v1 = g_xyzT[b*NN + n1];
        xs[n0]=v0.x; ys[n0]=v0.y; zs[n0]=v0.z;
        xs[n1]=v1.x; ys[n1]=v1.y; zs[n1]=v1.z;
        PACK2(px2[i], __float_as_uint(v0.x), __float_as_uint(v1.x));
        PACK2(py2[i], __float_as_uint(v0.y), __float_as_uint(v1.y));
        PACK2(pz2[i], __float_as_uint(v0.z), __float_as_uint(v1.z));
        dist[2*i] = 1e10f; dist[2*i+1] = 1e10f;
    }
    __syncthreads();
    int far = 0;
    float cx = xs[0], cy = ys[0], cz = zs[0];
    for (int s = 0; s < SS; s++) {
        if (tid == 0) {
            g_fps[b*SS + s] = far;
            g_newxyz[b*SS + s] = make_float4(cx, cy, cz, 0.f);
            out[(b*3+0)*SS + s] = cx;
            out[(b*3+1)*SS + s] = cy;
            out[(b*3+2)*SS + s] = cz;
        }
        u64 ncx2, ncy2, ncz2;
        {
            unsigned nx = __float_as_uint(-cx), ny = __float_as_uint(-cy), nz = __float_as_uint(-cz);
            PACK2(ncx2, nx, nx); PACK2(ncy2, ny, ny); PACK2(ncz2, nz, nz);
        }
        float bv = -1.f; int bi = 0;
        #pragma unroll
        for (int i = 0; i < 4; i++) {
            u64 dx2, dy2, dz2, t;
            ADD2(dx2, px2[i], ncx2);
            ADD2(dy2, py2[i], ncy2);
            ADD2(dz2, pz2[i], ncz2);
            MUL2(t, dx2, dx2);
            FMA2(t, dy2, dy2, t);
            FMA2(t, dz2, dz2, t);
            unsigned u0, u1; UNPACK2(u0, u1, t);
            float d0 = __uint_as_float(u0), d1 = __uint_as_float(u1);
            float nd0 = fminf(dist[2*i], d0);   dist[2*i] = nd0;
            if (nd0 > bv) { bv = nd0; bi = tid + 512*(2*i); }
            float nd1 = fminf(dist[2*i+1], d1); dist[2*i+1] = nd1;
            if (nd1 > bv) { bv = nd1; bi = tid + 512*(2*i+1); }
        }
        unsigned bb = __float_as_uint(bv);
        unsigned m  = __reduce_max_sync(0xffffffffu, bb);
        unsigned cand = (bb == m) ? (unsigned)bi : 0xffffffffu;
        unsigned mi = __reduce_min_sync(0xffffffffu, cand);
        int par = s & 1;
        if (lane == 0) { rv[par][w] = m; ri[par][w] = (int)mi; }
        __syncthreads();
        unsigned vv = (lane < 16) ? rv[par][lane] : 0u;
        int ii      = (lane < 16) ? ri[par][lane] : 0x7fffffff;
        unsigned m2 = __reduce_max_sync(0xffffffffu, vv);
        unsigned c2 = (vv == m2) ? (unsigned)ii : 0xffffffffu;
        unsigned mi2 = __reduce_min_sync(0xffffffffu, c2);
        far = (int)mi2;
        cx = xs[mi2]; cy = ys[mi2]; cz = zs[mi2];
    }
}

// -------- kNN (R14 passing version, unchanged)
__global__ __launch_bounds__(128, 6) void k_knn() {
    __shared__ u64 wkeys[4][32];
    __shared__ int sidx[32];
    __shared__ float sanchor[64];
    __shared__ double sred[8];
    int bs = blockIdx.x, b = bs >> 10;
    int tid = threadIdx.x, lane = tid & 31, w = tid >> 5;
    float4 cc = g_newxyz[bs];
    float cn = cc.x*cc.x + cc.y*cc.y + cc.z*cc.z;
    int nbase = w*1024 + lane;
    u64 cx2, cy2, cz2, cn2, m2c;
    {
        unsigned ux = __float_as_uint(cc.x), uy = __float_as_uint(cc.y), uz = __float_as_uint(cc.z);
        unsigned ucn = __float_as_uint(cn), um = __float_as_uint(-2.f);
        PACK2(cx2, ux, ux); PACK2(cy2, uy, uy); PACK2(cz2, uz, uz);
        PACK2(cn2, ucn, ucn); PACK2(m2c, um, um);
    }
    u64 d2[16];
    u64 kq0 = ~0ull, kq1 = ~0ull, kq2 = ~0ull;
    #pragma unroll
    for (int i = 0; i < 16; i++) {
        int n0 = nbase + 64*i, n1 = n0 + 32;
        float4 v0 = g_xyzT[b*NN + n0];
        float4 v1 = g_xyzT[b*NN + n1];
        u64 x2, y2, z2;
        PACK2(x2, __float_as_uint(v0.x), __float_as_uint(v1.x));
        PACK2(y2, __float_as_uint(v0.y), __float_as_uint(v1.y));
        PACK2(z2, __float_as_uint(v0.z), __float_as_uint(v1.z));
        u64 pn2, dt2, dd2;
        MUL2(pn2, x2, x2); FMA2(pn2, y2, y2, pn2); FMA2(pn2, z2, z2, pn2);
        MUL2(dt2, x2, cx2); FMA2(dt2, y2, cy2, dt2); FMA2(dt2, z2, cz2, dt2);
        ADD2(dd2, cn2, pn2);
        FMA2(dd2, dt2, m2c, dd2);
        d2[i] = dd2;
        unsigned ud0, ud1; UNPACK2(ud0, ud1, dd2);
        unsigned u0 = (ud0 & 0x80000000u) ? ~ud0 : (ud0 | 0x80000000u);
        u64 k0 = ((u64)u0 << 32) | (unsigned)n0;
        if (k0 < kq2) {
            if (k0 < kq1) { kq2 = kq1; if (k0 < kq0) { kq1 = kq0; kq0 = k0; } else kq1 = k0; }
            else kq2 = k0;
        }
        unsigned u1 = (ud1 & 0x80000000u) ? ~ud1 : (ud1 | 0x80000000u);
        u64 k1 = ((u64)u1 << 32) | (unsigned)n1;
        if (k1 < kq2) {
            if (k1 < kq1) { kq2 = kq1; if (k1 < kq0) { kq1 = kq0; kq0 = k1; } else kq1 = k1; }
            else kq2 = k1;
        }
    }
    unsigned mask = 0;
    for (int it = 0; it < KK; it++) {
        unsigned hi = (unsigned)(kq0 >> 32);
        unsigned m  = __reduce_min_sync(0xffffffffu, hi);
        unsigned cand = (hi == m) ? (unsigned)kq0 : 0xffffffffu;
        unsigned mi = __reduce_min_sync(0xffffffffu, cand);
        if (lane == 0) wkeys[w][it] = ((u64)m << 32) | mi;
        if (hi == m && (unsigned)kq0 == mi) {
            mask |= 1u << ((mi >> 5) & 31);
            kq0 = kq1; kq1 = kq2; kq2 = ~0ull;
            if (kq0 == ~0ull) {
                u64 best = ~0ull;
                #pragma unroll
                for (int i = 0; i < 16; i++) {
                    unsigned ud0, ud1; UNPACK2(ud0, ud1, d2[i]);
                    int j0 = 2*i, j1 = 2*i + 1;
                    if (!((mask >> j0) & 1u)) {
                        unsigned u = (ud0 & 0x80000000u) ? ~ud0 : (ud0 | 0x80000000u);
                        u64 k = ((u64)u << 32) | (unsigned)(nbase + 32*j0);
                        if (k < best) best = k;
                    }
                    if (!((mask >> j1) & 1u)) {
                        unsigned u = (ud1 & 0x80000000u) ? ~ud1 : (ud1 | 0x80000000u);
                        u64 k = ((u64)u << 32) | (unsigned)(nbase + 32*j1);
                        if (k < best) best = k;
                    }
                }
                kq0 = best;
            }
        }
    }
    int anc = g_fps[bs];
    if (tid >= 32 && tid < 48)
        *(float4*)&sanchor[(tid-32)*4] = *(const float4*)(g_featT + (size_t)(b*NN + anc)*DD + (tid-32)*4);
    __syncthreads();
    if (tid == 0) {
        int i0 = 0, i1 = 0, i2 = 0, i3 = 0;
        for (int t = 0; t < KK; t++) {
            u64 k0 = (i0 < 32) ? wkeys[0][i0] : ~0ull;
            u64 k1 = (i1 < 32) ? wkeys[1][i1] : ~0ull;
            u64 k2 = (i2 < 32) ? wkeys[2][i2] : ~0ull;
            u64 k3 = (i3 < 32) ? wkeys[3][i3] : ~0ull;
            u64 ka = (k0 <= k1) ? k0 : k1; int sa = (k0 <= k1) ? 0 : 1;
            u64 kb = (k2 <= k3) ? k2 : k3; int sb = (k2 <= k3) ? 2 : 3;
            u64 km; int sw_;
            if (ka <= kb) { km = ka; sw_ = sa; } else { km = kb; sw_ = sb; }
            sidx[t] = (int)(unsigned)(km & 0xffffffffull);
            if (sw_ == 0) i0++; else if (sw_ == 1) i1++; else if (sw_ == 2) i2++; else i3++;
        }
    }
    __syncthreads();
    if (tid < 32) g_knn[bs*KK + tid] = sidx[tid];
    double s = 0.0, q = 0.0;
    {
        int j = tid >> 2, ch0 = (tid & 3) << 4;
        const float* vr = g_featT + (size_t)(b*NN + sidx[j])*DD + ch0;
        #pragma unroll
        for (int t4 = 0; t4 < 4; t4++) {
            float4 v = *(const float4*)(vr + 4*t4);
            float4 a = *(const float4*)(&sanchor[ch0 + 4*t4]);
            float e0 = v.x-a.x, e1 = v.y-a.y, e2 = v.z-a.z, e3 = v.w-a.w;
            s += (double)e0 + (double)e1 + (double)e2 + (double)e3;
            q += (double)e0*(double)e0 + (double)e1*(double)e1
               + (double)e2*(double)e2 + (double)e3*(double)e3;
        }
    }
    if (tid < 32) {
        float4 pv = g_xyzT[b*NN + sidx[tid]];
        float e0 = pv.x-cc.x, e1 = pv.y-cc.y, e2 = pv.z-cc.z;
        s += (double)e0 + (double)e1 + (double)e2;
        q += (double)e0*(double)e0 + (double)e1*(double)e1 + (double)e2*(double)e2;
    }
    for (int off = 16; off; off >>= 1) {
        s += __shfl_down_sync(0xffffffffu, s, off);
        q += __shfl_down_sync(0xffffffffu, q, off);
    }
    if (lane == 0) { sred[w*2] = s; sred[w*2+1] = q; }
    __syncthreads();
    if (tid == 0) {
        double S = sred[0]+sred[2]+sred[4]+sred[6];
        double Q = sred[1]+sred[3]+sred[5]+sred[7];
        int slot = bs & 15;
        atomicAdd(&g_accStd[(b*16 + slot)*2],   S);
        atomicAdd(&g_accStd[(b*16 + slot)*2+1], Q);
    }
}

__global__ void k_stdfin() {
    int t = threadIdx.x;
    if (t < BB) {
        double S = 0, Q = 0;
        for (int sl = 0; sl < 16; sl++) {
            S += g_accStd[(t*16+sl)*2];
            Q += g_accStd[(t*16+sl)*2+1];
        }
        double n = (double)(SS * KK * 67);
        double mean = S / n;
        double var = (Q - S*mean) / (n - 1.0);
        g_invstd[t] = (float)(1.0 / (sqrt(var) + 1e-5));
    }
}

// 8 consecutive points (4 f32x2 pairs) x 8 outs; all-LDS.128 operand loads
__device__ __forceinline__ void mac88q(const float* Xs, const float* Ws2, int cinN,
                                       int qo, int oo, u64 acc2[4][8]) {
    #pragma unroll 2
    for (int i = 0; i < cinN; i++) {
        ulonglong2 A0 = *(const ulonglong2*)(Xs + i*256 + 8*qo);
        ulonglong2 A1 = *(const ulonglong2*)(Xs + i*256 + 8*qo + 4);
        const float* wrow = Ws2 + i*128 + 16*oo;
        ulonglong2 W0 = *(const ulonglong2*)(wrow);
        ulonglong2 W1 = *(const ulonglong2*)(wrow + 4);
        ulonglong2 W2 = *(const ulonglong2*)(wrow + 8);
        ulonglong2 W3 = *(const ulonglong2*)(wrow + 12);
        u64 a[4] = {A0.x, A0.y, A1.x, A1.y};
        u64 w[8] = {W0.x, W0.y, W1.x, W1.y, W2.x, W2.y, W3.x, W3.y};
        #pragma unroll
        for (int r = 0; r < 4; r++)
            #pragma unroll
            for (int c = 0; c < 8; c++)
                FMA2(acc2[r][c], a[r], w[c], acc2[r][c]);
    }
}

__device__ __forceinline__ void bn_reduce(float* sm, int tid, int qo, int oo,
                                          const float s[8], const float q[8],
                                          int which, int bidx) {
    __syncthreads();
    float2* red = (float2*)sm;
    #pragma unroll
    for (int c = 0; c < 8; c++)
        red[(oo*8+c)*33 + qo] = make_float2(s[c], q[c]);
    __syncthreads();
    if (tid < 64) {
        double S = 0, Q = 0;
        #pragma unroll
        for (int j = 0; j < 32; j++) { float2 f = red[tid*33 + j]; S += (double)f.x; Q += (double)f.y; }
        int slot = bidx & 31;
        double* acc = g_accBN + which * 32*64*2;
        atomicAdd(&acc[(slot*64+tid)*2],   S);
        atomicAdd(&acc[(slot*64+tid)*2+1], Q);
    }
}

__global__ __launch_bounds__(256) void k_conv1(
    const float* __restrict__ alpha, const float* __restrict__ beta,
    const float* __restrict__ w_tr, const float* __restrict__ b_tr)
{
    extern __shared__ float sm[];
    float* Xs  = sm;             // [131][256]
    float* Ws2 = sm + 131*256;   // [131][128]
    __shared__ int sn[256];
    __shared__ int sanc[8];
    __shared__ float4 scent[8];
    __shared__ float sal[68], sbe[68];
    int tid = threadIdx.x;
    int pbase = blockIdx.x * 256;
    int b = blockIdx.x >> 7;
    for (int idx = tid; idx < 64*131; idx += 256) {
        int o = idx / 131, i = idx - o*131;
        float wv = w_tr[idx];
        Ws2[i*128 + 2*o]     = wv;
        Ws2[i*128 + 2*o + 1] = wv;
    }
    sn[tid] = g_knn[pbase + tid];
    if (tid < 8) { int sg = blockIdx.x*8 + tid; sanc[tid] = g_fps[sg]; scent[tid] = g_newxyz[sg]; }
    if (tid < 67) { sal[tid] = alpha[tid]; sbe[tid] = beta[tid]; }
    float invs = g_invstd[b];
    __syncthreads();
    {
        int n = sn[tid], anc = sanc[tid >> 5];
        const float4* vr = (const float4*)(g_featT + (size_t)(b*NN + n)*DD);
        const float4* ar = (const float4*)(g_featT + (size_t)(b*NN + anc)*DD);
        #pragma unroll 4
        for (int j = 0; j < 16; j++) {
            float4 v = vr[j], a = ar[j];
            int c0 = 4*j;
            Xs[(c0+0)*256 + tid] = sal[c0+0]*((v.x - a.x)*invs) + sbe[c0+0];
            Xs[(c0+1)*256 + tid] = sal[c0+1]*((v.y - a.y)*invs) + sbe[c0+1];
            Xs[(c0+2)*256 + tid] = sal[c0+2]*((v.z - a.z)*invs) + sbe[c0+2];
            Xs[(c0+3)*256 + tid] = sal[c0+3]*((v.w - a.w)*invs) + sbe[c0+3];
            Xs[(67+c0+0)*256 + tid] = a.x;
            Xs[(67+c0+1)*256 + tid] = a.y;
            Xs[(67+c0+2)*256 + tid] = a.z;
            Xs[(67+c0+3)*256 + tid] = a.w;
        }
        float4 pv = g_xyzT[b*NN + n];
        float4 ct = scent[tid >> 5];
        Xs[64*256 + tid] = sal[64]*((pv.x - ct.x)*invs) + sbe[64];
        Xs[65*256 + tid] = sal[65]*((pv.y - ct.y)*invs) + sbe[65];
        Xs[66*256 + tid] = sal[66]*((pv.z - ct.z)*invs) + sbe[66];
    }
    __syncthreads();
    int qo = tid & 31, oo = tid >> 5;
    u64 acc2[4][8];
    #pragma unroll
    for (int r = 0; r < 4; r++)
        #pragma unroll
        for (int c = 0; c < 8; c++) acc2[r][c] = 0ull;
    mac88q(Xs, Ws2, 131, qo, oo, acc2);
    float4 bs0 = *(const float4*)(b_tr + oo*8);
    float4 bs1 = *(const float4*)(b_tr + oo*8 + 4);
    float bias[8] = {bs0.x,bs0.y,bs0.z,bs0.w,bs1.x,bs1.y,bs1.z,bs1.w};
    float ssum[8] = {0,0,0,0,0,0,0,0}, sq[8] = {0,0,0,0,0,0,0,0};
    #pragma unroll
    for (int r = 0; r < 4; r++) {
        int p0 = pbase + 8*qo + 2*r;
        float r0[8], r1[8];
        #pragma unroll
        for (int c = 0; c < 8; c++) {
            unsigned u0, u1; UNPACK2(u0, u1, acc2[r][c]);
            float v0 = __uint_as_float(u0) + bias[c];
            float v1 = __uint_as_float(u1) + bias[c];
            r0[c] = v0; r1[c] = v1;
            ssum[c] += v0 + v1; sq[c] += v0*v0 + v1*v1;
        }
        float* d0 = g_t1 + (size_t)p0*DD + oo*8;
        *(float4*)d0       = make_float4(r0[0],r0[1],r0[2],r0[3]);
        *(float4*)(d0 + 4) = make_float4(r0[4],r0[5],r0[6],r0[7]);
        float* d1 = d0 + DD;
        *(float4*)d1       = make_float4(r1[0],r1[1],r1[2],r1[3]);
        *(float4*)(d1 + 4) = make_float4(r1[4],r1[5],r1[6],r1[7]);
    }
    bn_reduce(sm, tid, qo, oo, ssum, sq, 0, blockIdx.x);
}

__global__ void k_bnfin(int which, const float* __restrict__ gam, const float* __restrict__ bet) {
    int c = threadIdx.x;
    if (c < 64) {
        const double* acc = g_accBN + which * 32*64*2;
        double S = 0, Q = 0;
        for (int sl = 0; sl < 32; sl++) { S += acc[(sl*64+c)*2]; Q += acc[(sl*64+c)*2+1]; }
        double Pn = (double)PP;
        double mean = S / Pn;
        double var = Q / Pn - mean*mean;
        double inv = 1.0 / sqrt(var + 1e-5);
        g_scale[which*64 + c] = (float)((double)gam[c] * inv);
        g_shift[which*64 + c] = (float)((double)bet[c] - mean * (double)gam[c] * inv);
    }
}

__global__ __launch_bounds__(256) void k_conv2(const float* __restrict__ w1, const float* __restrict__ b1) {
    extern __shared__ float sm[];
    float* Xs  = sm;
    float* Ws2 = sm + 64*256;
    __shared__ float ssc[64], ssh[64];
    int tid = threadIdx.x;
    int pbase = blockIdx.x * 256;
    for (int idx = tid; idx < 64*64; idx += 256) {
        int o = idx >> 6, i = idx & 63;
        float wv = w1[idx];
        Ws2[i*128 + 2*o] = wv; Ws2[i*128 + 2*o + 1] = wv;
    }
    if (tid < 64) { ssc[tid] = g_scale[tid]; ssh[tid] = g_shift[tid]; }
    __syncthreads();
    {
        const float4* tr = (const float4*)(g_t1 + (size_t)(pbase + tid)*DD);
        #pragma unroll 4
        for (int j = 0; j < 16; j++) {
            float4 v = tr[j];
            int c0 = 4*j;
            Xs[(c0+0)*256 + tid] = fmaxf(ssc[c0+0]*v.x + ssh[c0+0], 0.f);
            Xs[(c0+1)*256 + tid] = fmaxf(ssc[c0+1]*v.y + ssh[c0+1], 0.f);
            Xs[(c0+2)*256 + tid] = fmaxf(ssc[c0+2]*v.z + ssh[c0+2], 0.f);
            Xs[(c0+3)*256 + tid] = fmaxf(ssc[c0+3]*v.w + ssh[c0+3], 0.f);
        }
    }
    __syncthreads();
    int qo = tid & 31, oo = tid >> 5;
    u64 acc2[4][8];
    #pragma unroll
    for (int r = 0; r < 4; r++)
        #pragma unroll
        for (int c = 0; c < 8; c++) acc2[r][c] = 0ull;
    mac88q(Xs, Ws2, 64, qo, oo, acc2);
    float4 bs0 = *(const float4*)(b1 + oo*8);
    float4 bs1 = *(const float4*)(b1 + oo*8 + 4);
    float bias[8] = {bs0.x,bs0.y,bs0.z,bs0.w,bs1.x,bs1.y,bs1.z,bs1.w};
    float ssum[8] = {0,0,0,0,0,0,0,0}, sq[8] = {0,0,0,0,0,0,0,0};
    #pragma unroll
    for (int r = 0; r < 4; r++) {
        int p0 = pbase + 8*qo + 2*r;
        float r0[8], r1[8];
        #pragma unroll
        for (int c = 0; c < 8; c++) {
            unsigned u0, u1; UNPACK2(u0, u1, acc2[r][c]);
            float v0 = __uint_as_float(u0) + bias[c];
            float v1 = __uint_as_float(u1) + bias[c];
            r0[c] = v0; r1[c] = v1;
            ssum[c] += v0 + v1; sq[c] += v0*v0 + v1*v1;
        }
        float* d0 = g_t2 + (size_t)p0*DD + oo*8;
        *(float4*)d0       = make_float4(r0[0],r0[1],r0[2],r0[3]);
        *(float4*)(d0 + 4) = make_float4(r0[4],r0[5],r0[6],r0[7]);
        float* d1 = d0 + DD;
        *(float4*)d1       = make_float4(r1[0],r1[1],r1[2],r1[3]);
        *(float4*)(d1 + 4) = make_float4(r1[4],r1[5],r1[6],r1[7]);
    }
    bn_reduce(sm, tid, qo, oo, ssum, sq, 1, blockIdx.x);
}

__global__ __launch_bounds__(256) void k_conv3(const float* __restrict__ w2, const float* __restrict__ b2,
                                               float* __restrict__ outF) {
    extern __shared__ float sm[];
    float* Xs  = sm;
    float* Ws2 = sm + 64*256;
    __shared__ float ssc[64], ssh[64], ssc0[64], ssh0[64];
    int tid = threadIdx.x;
    int pbase = blockIdx.x * 256;
    for (int idx = tid; idx < 64*64; idx += 256) {
        int o = idx >> 6, i = idx & 63;
        float wv = w2[idx];
        Ws2[i*128 + 2*o] = wv; Ws2[i*128 + 2*o + 1] = wv;
    }
    if (tid < 64) {
        ssc[tid] = g_scale[64+tid]; ssh[tid] = g_shift[64+tid];
        ssc0[tid] = g_scale[tid];   ssh0[tid] = g_shift[tid];
    }
    __syncthreads();
    {
        const float4* tr = (const float4*)(g_t2 + (size_t)(pbase + tid)*DD);
        #pragma unroll 4
        for (int j = 0; j < 16; j++) {
            float4 v = tr[j];
            int c0 = 4*j;
            Xs[(c0+0)*256 + tid] = fmaxf(ssc[c0+0]*v.x + ssh[c0+0], 0.f);
            Xs[(c0+1)*256 + tid] = fmaxf(ssc[c0+1]*v.y + ssh[c0+1], 0.f);
            Xs[(c0+2)*256 + tid] = fmaxf(ssc[c0+2]*v.z + ssh[c0+2], 0.f);
            Xs[(c0+3)*256 + tid] = fmaxf(ssc[c0+3]*v.w + ssh[c0+3], 0.f);
        }
    }
    __syncthreads();
    int qo = tid & 31, oo = tid >> 5;
    u64 acc2[4][8];
    #pragma unroll
    for (int r = 0; r < 4; r++)
        #pragma unroll
        for (int c = 0; c < 8; c++) acc2[r][c] = 0ull;
    mac88q(Xs, Ws2, 64, qo, oo, acc2);
    float4 bs0 = *(const float4*)(b2 + oo*8);
    float4 bs1 = *(const float4*)(b2 + oo*8 + 4);
    float bias[8] = {bs0.x,bs0.y,bs0.z,bs0.w,bs1.x,bs1.y,bs1.z,bs1.w};
    float sc1[8], sh1[8];
    #pragma unroll
    for (int c = 0; c < 8; c++) { sc1[c] = ssc0[oo*8+c]; sh1[c] = ssh0[oo*8+c]; }
    float mx[8] = {0,0,0,0,0,0,0,0};   // relu outputs are >= 0
    #pragma unroll
    for (int r = 0; r < 4; r++) {
        int p0 = pbase + 8*qo + 2*r;
        const float* t1p = g_t1 + (size_t)p0*DD + oo*8;
        float4 a0 = *(const float4*)t1p;
        float4 a1 = *(const float4*)(t1p + 4);
        float4 b0 = *(const float4*)(t1p + DD);
        float4 b1v = *(const float4*)(t1p + DD + 4);
        float t10[8] = {a0.x,a0.y,a0.z,a0.w,a1.x,a1.y,a1.z,a1.w};
        float t11[8] = {b0.x,b0.y,b0.z,b0.w,b1v.x,b1v.y,b1v.z,b1v.w};
        #pragma unroll
        for (int c = 0; c < 8; c++) {
            unsigned u0, u1; UNPACK2(u0, u1, acc2[r][c]);
            float res0 = fmaxf(sc1[c]*t10[c] + sh1[c], 0.f);
            float res1 = fmaxf(sc1[c]*t11[c] + sh1[c], 0.f);
            float v0 = fmaxf(__uint_as_float(u0) + bias[c] + res0, 0.f);
            float v1 = fmaxf(__uint_as_float(u1) + bias[c] + res1, 0.f);
            mx[c] = fmaxf(mx[c], fmaxf(v0, v1));
        }
    }
    int sg = blockIdx.x*8 + (qo >> 2);
    int ob = sg >> 10, os = sg & 1023;
    #pragma unroll
    for (int c = 0; c < 8; c++) {
        float mm = mx[c];
        mm = fmaxf(mm, __shfl_xor_sync(0xffffffffu, mm, 1));
        mm = fmaxf(mm, __shfl_xor_sync(0xffffffffu, mm, 2));
        if ((qo & 3) == 0)
            outF[(size_t)(ob*DD + oo*8 + c)*SS + os] = mm;
    }
}

extern "C" void kernel_launch(void* const* d_in, const int* in_sizes, int n_in,
                              void* d_out, int out_size) {
    const float* xyz   = (const float*)d_in[0];
    const float* feat  = (const float*)d_in[1];
    const float* alpha = (const float*)d_in[2];
    const float* beta  = (const float*)d_in[3];
    const float* w_tr  = (const float*)d_in[4];
    const float* b_tr  = (const float*)d_in[5];
    const float* g_tr  = (const float*)d_in[6];
    const float* be_tr = (const float*)d_in[7];
    const float* w1    = (const float*)d_in[8];
    const float* b1    = (const float*)d_in[9];
    const float* g1    = (const float*)d_in[10];
    const float* be1   = (const float*)d_in[11];
    const float* w2    = (const float*)d_in[12];
    const float* b2    = (const float*)d_in[13];
    float* out = (float*)d_out;
    float* outF = out + BB*3*SS;

    const int SM1 = (131*256 + 131*128) * 4;
    const int SM2 = (64*256 + 64*128) * 4;

    static cudaStream_t s2 = nullptr;
    static cudaEvent_t evA = nullptr, evB = nullptr;
    if (!s2) {
        cudaFuncSetAttribute(k_fps,  cudaFuncAttributeMaxDynamicSharedMemorySize, 3*NN*4);
        cudaFuncSetAttribute(k_conv1, cudaFuncAttributeMaxDynamicSharedMemorySize, SM1);
        cudaFuncSetAttribute(k_conv2, cudaFuncAttributeMaxDynamicSharedMemorySize, SM2);
        cudaFuncSetAttribute(k_conv3, cudaFuncAttributeMaxDynamicSharedMemorySize, SM2);
        cudaStreamCreateWithFlags(&s2, cudaStreamNonBlocking);
        cudaEventCreateWithFlags(&evA, cudaEventDisableTiming);
        cudaEventCreateWithFlags(&evB, cudaEventDisableTiming);
    }

    k_txyz<<<BB*NN/256, 256>>>(xyz);
    cudaEventRecord(evA, 0);
    cudaStreamWaitEvent(s2, evA, 0);
    {
        dim3 g(NN/32, DD/32, BB), t(32, 8);
        k_tfeat<<<g, t, 0, s2>>>(feat);   // overlaps with k_fps
    }
    cudaEventRecord(evB, s2);
    k_fps<<<BB, 512, 3*NN*4>>>(out);
    cudaStreamWaitEvent(0, evB, 0);
    k_knn<<<BB*SS, 128>>>();
    k_stdfin<<<1, 32>>>();
    k_conv1<<<PP/256, 256, SM1>>>(alpha, beta, w_tr, b_tr);
    k_bnfin<<<1, 64>>>(0, g_tr, be_tr);
    k_conv2<<<PP/256, 256, SM2>>>(w1, b1);
    k_bnfin<<<1, 64>>>(1, g1, be1);
    k_conv3<<<PP/256, 256, SM2>>>(w2, b2, outF);
}

// round 16
// speedup vs baseline: 1.0238x; 1.0238x over previous
#include <cuda_runtime.h>
#include <math.h>

#define BB 8
#define NN 4096
#define DD 64
#define SS 1024
#define KK 32
#define PP (BB*SS*KK)

typedef unsigned long long u64;
#define PACK2(out, lo, hi) asm("mov.b64 %0, {%1, %2};" : "=l"(out) : "r"(lo), "r"(hi))
#define UNPACK2(lo, hi, in) asm("mov.b64 {%0, %1}, %2;" : "=r"(lo), "=r"(hi) : "l"(in))
#define MUL2(out, a, b) asm("mul.rn.f32x2 %0, %1, %2;" : "=l"(out) : "l"(a), "l"(b))
#define ADD2(out, a, b) asm("add.rn.f32x2 %0, %1, %2;" : "=l"(out) : "l"(a), "l"(b))
#define FMA2(out, a, b, c) asm("fma.rn.f32x2 %0, %1, %2, %3;" : "=l"(out) : "l"(a), "l"(b), "l"(c))

static __device__ float4 g_xyzT[BB*NN];
static __device__ float  g_featT[BB*NN*DD];
static __device__ float4 g_newxyz[BB*SS];
static __device__ int    g_fps[BB*SS];
static __device__ int    g_knn[BB*SS*KK];
static __device__ double g_accStd[BB*16*2];
static __device__ double g_accBN[2*32*64*2];
static __device__ float  g_invstd[BB];
static __device__ float  g_scale[2*64];
static __device__ float  g_shift[2*64];
static __device__ float  g_t1[(size_t)PP*DD];
static __device__ float  g_t2[(size_t)PP*DD];

__global__ void k_txyz(const float* __restrict__ xyz) {
    int tid = threadIdx.x;
    int t = blockIdx.x * 256 + tid;
    if (blockIdx.x == 0) {
        for (int i = tid; i < BB*16*2; i += 256) g_accStd[i] = 0.0;
        for (int i = tid; i < 2*32*64*2; i += 256) g_accBN[i] = 0.0;
    }
    int b = t >> 12, n = t & (NN-1);
    const float* p = xyz + b * 3 * NN;
    g_xyzT[t] = make_float4(p[n], p[NN+n], p[2*NN+n], 0.f);
}

__global__ void k_tfeat(const float* __restrict__ f) {
    __shared__ float tile[32][33];
    int b = blockIdx.z, c0 = blockIdx.y * 32, n0 = blockIdx.x * 32;
    int tx = threadIdx.x, ty = threadIdx.y;
    #pragma unroll
    for (int i = 0; i < 32; i += 8)
        tile[ty+i][tx] = f[(b*DD + c0+ty+i) * NN + n0 + tx];
    __syncthreads();
    #pragma unroll
    for (int i = 0; i < 32; i += 8)
        g_featT[(size_t)(b*NN + n0+ty+i) * DD + c0 + tx] = tile[tx][ty+i];
}

// -------- FPS: 512 threads, packed f32x2, single barrier per iter (unchanged)
__global__ __launch_bounds__(512) void k_fps(float* __restrict__ out) {
    extern __shared__ float sm[];
    float* xs = sm; float* ys = sm + NN; float* zs = sm + 2*NN;
    __shared__ unsigned rv[2][16]; __shared__ int ri[2][16];
    int b = blockIdx.x, tid = threadIdx.x;
    int lane = tid & 31, w = tid >> 5;
    u64 px2[4], py2[4], pz2[4];
    float dist[8];
    #pragma unroll
    for (int i = 0; i < 4; i++) {
        int n0 = tid + 512*(2*i), n1 = n0 + 512;
        float4 v0 = g_xyzT[b*NN + n0];
        float4 v1 = g_xyzT[b*NN + n1];
        xs[n0]=v0.x; ys[n0]=v0.y; zs[n0]=v0.z;
        xs[n1]=v1.x; ys[n1]=v1.y; zs[n1]=v1.z;
        PACK2(px2[i], __float_as_uint(v0.x), __float_as_uint(v1.x));
        PACK2(py2[i], __float_as_uint(v0.y), __float_as_uint(v1.y));
        PACK2(pz2[i], __float_as_uint(v0.z), __float_as_uint(v1.z));
        dist[2*i] = 1e10f; dist[2*i+1] = 1e10f;
    }
    __syncthreads();
    int far = 0;
    float cx = xs[0], cy = ys[0], cz = zs[0];
    for (int s = 0; s < SS; s++) {
        if (tid == 0) {
            g_fps[b*SS + s] = far;
            g_newxyz[b*SS + s] = make_float4(cx, cy, cz, 0.f);
            out[(b*3+0)*SS + s] = cx;
            out[(b*3+1)*SS + s] = cy;
            out[(b*3+2)*SS + s] = cz;
        }
        u64 ncx2, ncy2, ncz2;
        {
            unsigned nx = __float_as_uint(-cx), ny = __float_as_uint(-cy), nz = __float_as_uint(-cz);
            PACK2(ncx2, nx, nx); PACK2(ncy2, ny, ny); PACK2(ncz2, nz, nz);
        }
        float bv = -1.f; int bi = 0;
        #pragma unroll
        for (int i = 0; i < 4; i++) {
            u64 dx2, dy2, dz2, t;
            ADD2(dx2, px2[i], ncx2);
            ADD2(dy2, py2[i], ncy2);
            ADD2(dz2, pz2[i], ncz2);
            MUL2(t, dx2, dx2);
            FMA2(t, dy2, dy2, t);
            FMA2(t, dz2, dz2, t);
            unsigned u0, u1; UNPACK2(u0, u1, t);
            float d0 = __uint_as_float(u0), d1 = __uint_as_float(u1);
            float nd0 = fminf(dist[2*i], d0);   dist[2*i] = nd0;
            if (nd0 > bv) { bv = nd0; bi = tid + 512*(2*i); }
            float nd1 = fminf(dist[2*i+1], d1); dist[2*i+1] = nd1;
            if (nd1 > bv) { bv = nd1; bi = tid + 512*(2*i+1); }
        }
        unsigned bb = __float_as_uint(bv);
        unsigned m  = __reduce_max_sync(0xffffffffu, bb);
        unsigned cand = (bb == m) ? (unsigned)bi : 0xffffffffu;
        unsigned mi = __reduce_min_sync(0xffffffffu, cand);
        int par = s & 1;
        if (lane == 0) { rv[par][w] = m; ri[par][w] = (int)mi; }
        __syncthreads();
        unsigned vv = (lane < 16) ? rv[par][lane] : 0u;
        int ii      = (lane < 16) ? ri[par][lane] : 0x7fffffff;
        unsigned m2 = __reduce_max_sync(0xffffffffu, vv);
        unsigned c2 = (vv == m2) ? (unsigned)ii : 0xffffffffu;
        unsigned mi2 = __reduce_min_sync(0xffffffffu, c2);
        far = (int)mi2;
        cx = xs[mi2]; cy = ys[mi2]; cz = zs[mi2];
    }
}

// -------- kNN: f32x2 dists, top-3 queues, occ-8, parallel rank merge
__global__ __launch_bounds__(128, 8) void k_knn() {
    __shared__ u64 wkeys[4][32];
    __shared__ int sidx[32];
    __shared__ float sanchor[64];
    __shared__ double sred[8];
    int bs = blockIdx.x, b = bs >> 10;
    int tid = threadIdx.x, lane = tid & 31, w = tid >> 5;
    float4 cc = g_newxyz[bs];
    float cn = cc.x*cc.x + cc.y*cc.y + cc.z*cc.z;
    int nbase = w*1024 + lane;
    u64 cx2, cy2, cz2, cn2, m2c;
    {
        unsigned ux = __float_as_uint(cc.x), uy = __float_as_uint(cc.y), uz = __float_as_uint(cc.z);
        unsigned ucn = __float_as_uint(cn), um = __float_as_uint(-2.f);
        PACK2(cx2, ux, ux); PACK2(cy2, uy, uy); PACK2(cz2, uz, uz);
        PACK2(cn2, ucn, ucn); PACK2(m2c, um, um);
    }
    u64 d2[16];
    u64 kq0 = ~0ull, kq1 = ~0ull, kq2 = ~0ull;
    #pragma unroll
    for (int i = 0; i < 16; i++) {
        int n0 = nbase + 64*i, n1 = n0 + 32;
        float4 v0 = g_xyzT[b*NN + n0];
        float4 v1 = g_xyzT[b*NN + n1];
        u64 x2, y2, z2;
        PACK2(x2, __float_as_uint(v0.x), __float_as_uint(v1.x));
        PACK2(y2, __float_as_uint(v0.y), __float_as_uint(v1.y));
        PACK2(z2, __float_as_uint(v0.z), __float_as_uint(v1.z));
        u64 pn2, dt2, dd2;
        MUL2(pn2, x2, x2); FMA2(pn2, y2, y2, pn2); FMA2(pn2, z2, z2, pn2);
        MUL2(dt2, x2, cx2); FMA2(dt2, y2, cy2, dt2); FMA2(dt2, z2, cz2, dt2);
        ADD2(dd2, cn2, pn2);
        FMA2(dd2, dt2, m2c, dd2);
        d2[i] = dd2;
        unsigned ud0, ud1; UNPACK2(ud0, ud1, dd2);
        unsigned u0 = (ud0 & 0x80000000u) ? ~ud0 : (ud0 | 0x80000000u);
        u64 k0 = ((u64)u0 << 32) | (unsigned)n0;
        if (k0 < kq2) {
            if (k0 < kq1) { kq2 = kq1; if (k0 < kq0) { kq1 = kq0; kq0 = k0; } else kq1 = k0; }
            else kq2 = k0;
        }
        unsigned u1 = (ud1 & 0x80000000u) ? ~ud1 : (ud1 | 0x80000000u);
        u64 k1 = ((u64)u1 << 32) | (unsigned)n1;
        if (k1 < kq2) {
            if (k1 < kq1) { kq2 = kq1; if (k1 < kq0) { kq1 = kq0; kq0 = k1; } else kq1 = k1; }
            else kq2 = k1;
        }
    }
    unsigned mask = 0;
    for (int it = 0; it < KK; it++) {
        unsigned hi = (unsigned)(kq0 >> 32);
        unsigned m  = __reduce_min_sync(0xffffffffu, hi);
        unsigned cand = (hi == m) ? (unsigned)kq0 : 0xffffffffu;
        unsigned mi = __reduce_min_sync(0xffffffffu, cand);
        if (lane == 0) wkeys[w][it] = ((u64)m << 32) | mi;
        if (hi == m && (unsigned)kq0 == mi) {
            mask |= 1u << ((mi >> 5) & 31);
            kq0 = kq1; kq1 = kq2; kq2 = ~0ull;
            if (kq0 == ~0ull) {                 // rare: refill top-1 by rescan
                u64 best = ~0ull;
                #pragma unroll
                for (int i = 0; i < 16; i++) {
                    unsigned ud0, ud1; UNPACK2(ud0, ud1, d2[i]);
                    int j0 = 2*i, j1 = 2*i + 1;
                    if (!((mask >> j0) & 1u)) {
                        unsigned u = (ud0 & 0x80000000u) ? ~ud0 : (ud0 | 0x80000000u);
                        u64 k = ((u64)u << 32) | (unsigned)(nbase + 32*j0);
                        if (k < best) best = k;
                    }
                    if (!((mask >> j1) & 1u)) {
                        unsigned u = (ud1 & 0x80000000u) ? ~ud1 : (ud1 | 0x80000000u);
                        u64 k = ((u64)u << 32) | (unsigned)(nbase + 32*j1);
                        if (k < best) best = k;
                    }
                }
                kq0 = best;
            }
        }
    }
    int anc = g_fps[bs];
    if (tid >= 32 && tid < 48)
        *(float4*)&sanchor[(tid-32)*4] = *(const float4*)(g_featT + (size_t)(b*NN + anc)*DD + (tid-32)*4);
    __syncthreads();
    // Parallel rank merge: each candidate counts elements smaller than it
    {
        u64 key = wkeys[w][lane];
        int rank = lane;   // position within own sorted list
        #pragma unroll
        for (int v = 1; v < 4; v++) {
            const u64* arr = wkeys[(w + v) & 3];
            int pos = 0;
            if (arr[pos + 15] < key) pos += 16;
            if (arr[pos + 7]  < key) pos += 8;
            if (arr[pos + 3]  < key) pos += 4;
            if (arr[pos + 1]  < key) pos += 2;
            if (arr[pos]      < key) pos += 1;
            if (arr[pos]      < key) pos += 1;
            rank += pos;
        }
        if (rank < KK) sidx[rank] = (int)(unsigned)key;
    }
    __syncthreads();
    if (tid < 32) g_knn[bs*KK + tid] = sidx[tid];
    // fused std accumulation
    double s = 0.0, q = 0.0;
    {
        int j = tid >> 2, ch0 = (tid & 3) << 4;
        const float* vr = g_featT + (size_t)(b*NN + sidx[j])*DD + ch0;
        #pragma unroll
        for (int t4 = 0; t4 < 4; t4++) {
            float4 v = *(const float4*)(vr + 4*t4);
            float4 a = *(const float4*)(&sanchor[ch0 + 4*t4]);
            float e0 = v.x-a.x, e1 = v.y-a.y, e2 = v.z-a.z, e3 = v.w-a.w;
            s += (double)e0 + (double)e1 + (double)e2 + (double)e3;
            q += (double)e0*(double)e0 + (double)e1*(double)e1
               + (double)e2*(double)e2 + (double)e3*(double)e3;
        }
    }
    if (tid < 32) {
        float4 pv = g_xyzT[b*NN + sidx[tid]];
        float e0 = pv.x-cc.x, e1 = pv.y-cc.y, e2 = pv.z-cc.z;
        s += (double)e0 + (double)e1 + (double)e2;
        q += (double)e0*(double)e0 + (double)e1*(double)e1 + (double)e2*(double)e2;
    }
    for (int off = 16; off; off >>= 1) {
        s += __shfl_down_sync(0xffffffffu, s, off);
        q += __shfl_down_sync(0xffffffffu, q, off);
    }
    if (lane == 0) { sred[w*2] = s; sred[w*2+1] = q; }
    __syncthreads();
    if (tid == 0) {
        double S = sred[0]+sred[2]+sred[4]+sred[6];
        double Q = sred[1]+sred[3]+sred[5]+sred[7];
        int slot = bs & 15;
        atomicAdd(&g_accStd[(b*16 + slot)*2],   S);
        atomicAdd(&g_accStd[(b*16 + slot)*2+1], Q);
    }
}

__global__ void k_stdfin() {
    int t = threadIdx.x;
    if (t < BB) {
        double S = 0, Q = 0;
        for (int sl = 0; sl < 16; sl++) {
            S += g_accStd[(t*16+sl)*2];
            Q += g_accStd[(t*16+sl)*2+1];
        }
        double n = (double)(SS * KK * 67);
        double mean = S / n;
        double var = (Q - S*mean) / (n - 1.0);
        g_invstd[t] = (float)(1.0 / (sqrt(var) + 1e-5));
    }
}

// R14 MAC: strided pairs, LDS.64 a + broadcast LDS.64 w (known-good)
__device__ __forceinline__ void mac88p(const float* Xs, const float* Ws2, int cinN,
                                       int qo, int oo, u64 acc2[4][8]) {
    #pragma unroll 2
    for (int i = 0; i < cinN; i++) {
        u64 a2[4];
        #pragma unroll
        for (int r = 0; r < 4; r++)
            a2[r] = *(const u64*)(Xs + i*256 + 2*(qo + 32*r));
        #pragma unroll
        for (int c = 0; c < 8; c++) {
            u64 w2 = *(const u64*)(Ws2 + i*128 + 2*(oo*8 + c));
            #pragma unroll
            for (int r = 0; r < 4; r++)
                FMA2(acc2[r][c], a2[r], w2, acc2[r][c]);
        }
    }
}

__device__ __forceinline__ void bn_reduce(float* sm, int tid, int qo, int oo,
                                          const float s[8], const float q[8],
                                          int which, int bidx) {
    __syncthreads();
    float2* red = (float2*)sm;
    #pragma unroll
    for (int c = 0; c < 8; c++)
        red[(oo*8+c)*33 + qo] = make_float2(s[c], q[c]);
    __syncthreads();
    if (tid < 64) {
        double S = 0, Q = 0;
        #pragma unroll
        for (int j = 0; j < 32; j++) { float2 f = red[tid*33 + j]; S += (double)f.x; Q += (double)f.y; }
        int slot = bidx & 31;
        double* acc = g_accBN + which * 32*64*2;
        atomicAdd(&acc[(slot*64+tid)*2],   S);
        atomicAdd(&acc[(slot*64+tid)*2+1], Q);
    }
}

__global__ __launch_bounds__(256) void k_conv1(
    const float* __restrict__ alpha, const float* __restrict__ beta,
    const float* __restrict__ w_tr, const float* __restrict__ b_tr)
{
    extern __shared__ float sm[];
    float* Xs  = sm;             // [131][256]
    float* Ws2 = sm + 131*256;   // [131][128]
    __shared__ int sn[256];
    __shared__ int sanc[8];
    __shared__ float4 scent[8];
    __shared__ float sal[68], sbe[68];
    int tid = threadIdx.x;
    int pbase = blockIdx.x * 256;
    int b = blockIdx.x >> 7;
    for (int idx = tid; idx < 64*131; idx += 256) {
        int o = idx / 131, i = idx - o*131;
        float wv = w_tr[idx];
        Ws2[i*128 + 2*o]     = wv;
        Ws2[i*128 + 2*o + 1] = wv;
    }
    sn[tid] = g_knn[pbase + tid];
    if (tid < 8) { int sg = blockIdx.x*8 + tid; sanc[tid] = g_fps[sg]; scent[tid] = g_newxyz[sg]; }
    if (tid < 67) { sal[tid] = alpha[tid]; sbe[tid] = beta[tid]; }
    float invs = g_invstd[b];
    __syncthreads();
    {
        int n = sn[tid], anc = sanc[tid >> 5];
        const float4* vr = (const float4*)(g_featT + (size_t)(b*NN + n)*DD);
        const float4* ar = (const float4*)(g_featT + (size_t)(b*NN + anc)*DD);
        #pragma unroll 4
        for (int j = 0; j < 16; j++) {
            float4 v = vr[j], a = ar[j];
            int c0 = 4*j;
            Xs[(c0+0)*256 + tid] = sal[c0+0]*((v.x - a.x)*invs) + sbe[c0+0];
            Xs[(c0+1)*256 + tid] = sal[c0+1]*((v.y - a.y)*invs) + sbe[c0+1];
            Xs[(c0+2)*256 + tid] = sal[c0+2]*((v.z - a.z)*invs) + sbe[c0+2];
            Xs[(c0+3)*256 + tid] = sal[c0+3]*((v.w - a.w)*invs) + sbe[c0+3];
            Xs[(67+c0+0)*256 + tid] = a.x;
            Xs[(67+c0+1)*256 + tid] = a.y;
            Xs[(67+c0+2)*256 + tid] = a.z;
            Xs[(67+c0+3)*256 + tid] = a.w;
        }
        float4 pv = g_xyzT[b*NN + n];
        float4 ct = scent[tid >> 5];
        Xs[64*256 + tid] = sal[64]*((pv.x - ct.x)*invs) + sbe[64];
        Xs[65*256 + tid] = sal[65]*((pv.y - ct.y)*invs) + sbe[65];
        Xs[66*256 + tid] = sal[66]*((pv.z - ct.z)*invs) + sbe[66];
    }
    __syncthreads();
    int qo = tid & 31, oo = tid >> 5;
    u64 acc2[4][8];
    #pragma unroll
    for (int r = 0; r < 4; r++)
        #pragma unroll
        for (int c = 0; c < 8; c++) acc2[r][c] = 0ull;
    mac88p(Xs, Ws2, 131, qo, oo, acc2);
    float4 bs0 = *(const float4*)(b_tr + oo*8);
    float4 bs1 = *(const float4*)(b_tr + oo*8 + 4);
    float bias[8] = {bs0.x,bs0.y,bs0.z,bs0.w,bs1.x,bs1.y,bs1.z,bs1.w};
    float ssum[8] = {0,0,0,0,0,0,0,0}, sq[8] = {0,0,0,0,0,0,0,0};
    #pragma unroll
    for (int r = 0; r < 4; r++) {
        int p0 = pbase + 2*(qo + 32*r);
        float r0[8], r1[8];
        #pragma unroll
        for (int c = 0; c < 8; c++) {
            unsigned u0, u1; UNPACK2(u0, u1, acc2[r][c]);
            float v0 = __uint_as_float(u0) + bias[c];
            float v1 = __uint_as_float(u1) + bias[c];
            r0[c] = v0; r1[c] = v1;
            ssum[c] += v0 + v1; sq[c] += v0*v0 + v1*v1;
        }
        float* d0 = g_t1 + (size_t)p0*DD + oo*8;
        *(float4*)d0       = make_float4(r0[0],r0[1],r0[2],r0[3]);
        *(float4*)(d0 + 4) = make_float4(r0[4],r0[5],r0[6],r0[7]);
        float* d1 = d0 + DD;
        *(float4*)d1       = make_float4(r1[0],r1[1],r1[2],r1[3]);
        *(float4*)(d1 + 4) = make_float4(r1[4],r1[5],r1[6],r1[7]);
    }
    bn_reduce(sm, tid, qo, oo, ssum, sq, 0, blockIdx.x);
}

__global__ void k_bnfin(int which, const float* __restrict__ gam, const float* __restrict__ bet) {
    int c = threadIdx.x;
    if (c < 64) {
        const double* acc = g_accBN + which * 32*64*2;
        double S = 0, Q = 0;
        for (int sl = 0; sl < 32; sl++) { S += acc[(sl*64+c)*2]; Q += acc[(sl*64+c)*2+1]; }
        double Pn = (double)PP;
        double mean = S / Pn;
        double var = Q / Pn - mean*mean;
        double inv = 1.0 / sqrt(var + 1e-5);
        g_scale[which*64 + c] = (float)((double)gam[c] * inv);
        g_shift[which*64 + c] = (float)((double)bet[c] - mean * (double)gam[c] * inv);
    }
}

__global__ __launch_bounds__(256) void k_conv2(const float* __restrict__ w1, const float* __restrict__ b1) {
    extern __shared__ float sm[];
    float* Xs  = sm;
    float* Ws2 = sm + 64*256;
    __shared__ float ssc[64], ssh[64];
    int tid = threadIdx.x;
    int pbase = blockIdx.x * 256;
    for (int idx = tid; idx < 64*64; idx += 256) {
        int o = idx >> 6, i = idx & 63;
        float wv = w1[idx];
        Ws2[i*128 + 2*o] = wv; Ws2[i*128 + 2*o + 1] = wv;
    }
    if (tid < 64) { ssc[tid] = g_scale[tid]; ssh[tid] = g_shift[tid]; }
    __syncthreads();
    {
        const float4* tr = (const float4*)(g_t1 + (size_t)(pbase + tid)*DD);
        #pragma unroll 4
        for (int j = 0; j < 16; j++) {
            float4 v = tr[j];
            int c0 = 4*j;
            Xs[(c0+0)*256 + tid] = fmaxf(ssc[c0+0]*v.x + ssh[c0+0], 0.f);
            Xs[(c0+1)*256 + tid] = fmaxf(ssc[c0+1]*v.y + ssh[c0+1], 0.f);
            Xs[(c0+2)*256 + tid] = fmaxf(ssc[c0+2]*v.z + ssh[c0+2], 0.f);
            Xs[(c0+3)*256 + tid] = fmaxf(ssc[c0+3]*v.w + ssh[c0+3], 0.f);
        }
    }
    __syncthreads();
    int qo = tid & 31, oo = tid >> 5;
    u64 acc2[4][8];
    #pragma unroll
    for (int r = 0; r < 4; r++)
        #pragma unroll
        for (int c = 0; c < 8; c++) acc2[r][c] = 0ull;
    mac88p(Xs, Ws2, 64, qo, oo, acc2);
    float4 bs0 = *(const float4*)(b1 + oo*8);
    float4 bs1 = *(const float4*)(b1 + oo*8 + 4);
    float bias[8] = {bs0.x,bs0.y,bs0.z,bs0.w,bs1.x,bs1.y,bs1.z,bs1.w};
    float ssum[8] = {0,0,0,0,0,0,0,0}, sq[8] = {0,0,0,0,0,0,0,0};
    #pragma unroll
    for (int r = 0; r < 4; r++) {
        int p0 = pbase + 2*(qo + 32*r);
        float r0[8], r1[8];
        #pragma unroll
        for (int c = 0; c < 8; c++) {
            unsigned u0, u1; UNPACK2(u0, u1, acc2[r][c]);
            float v0 = __uint_as_float(u0) + bias[c];
            float v1 = __uint_as_float(u1) + bias[c];
            r0[c] = v0; r1[c] = v1;
            ssum[c] += v0 + v1; sq[c] += v0*v0 + v1*v1;
        }
        float* d0 = g_t2 + (size_t)p0*DD + oo*8;
        *(float4*)d0       = make_float4(r0[0],r0[1],r0[2],r0[3]);
        *(float4*)(d0 + 4) = make_float4(r0[4],r0[5],r0[6],r0[7]);
        float* d1 = d0 + DD;
        *(float4*)d1       = make_float4(r1[0],r1[1],r1[2],r1[3]);
        *(float4*)(d1 + 4) = make_float4(r1[4],r1[5],r1[6],r1[7]);
    }
    bn_reduce(sm, tid, qo, oo, ssum, sq, 1, blockIdx.x);
}

__global__ __launch_bounds__(256) void k_conv3(const float* __restrict__ w2, const float* __restrict__ b2,
                                               float* __restrict__ outF) {
    extern __shared__ float sm[];
    float* Xs  = sm;
    float* Ws2 = sm + 64*256;
    __shared__ float ssc[64], ssh[64], ssc0[64], ssh0[64];
    int tid = threadIdx.x;
    int pbase = blockIdx.x * 256;
    for (int idx = tid; idx < 64*64; idx += 256) {
        int o = idx >> 6, i = idx & 63;
        float wv = w2[idx];
        Ws2[i*128 + 2*o] = wv; Ws2[i*128 + 2*o + 1] = wv;
    }
    if (tid < 64) {
        ssc[tid] = g_scale[64+tid]; ssh[tid] = g_shift[64+tid];
        ssc0[tid] = g_scale[tid];   ssh0[tid] = g_shift[tid];
    }
    __syncthreads();
    {
        const float4* tr = (const float4*)(g_t2 + (size_t)(pbase + tid)*DD);
        #pragma unroll 4
        for (int j = 0; j < 16; j++) {
            float4 v = tr[j];
            int c0 = 4*j;
            Xs[(c0+0)*256 + tid] = fmaxf(ssc[c0+0]*v.x + ssh[c0+0], 0.f);
            Xs[(c0+1)*256 + tid] = fmaxf(ssc[c0+1]*v.y + ssh[c0+1], 0.f);
            Xs[(c0+2)*256 + tid] = fmaxf(ssc[c0+2]*v.z + ssh[c0+2], 0.f);
            Xs[(c0+3)*256 + tid] = fmaxf(ssc[c0+3]*v.w + ssh[c0+3], 0.f);
        }
    }
    __syncthreads();
    int qo = tid & 31, oo = tid >> 5;
    u64 acc2[4][8];
    #pragma unroll
    for (int r = 0; r < 4; r++)
        #pragma unroll
        for (int c = 0; c < 8; c++) acc2[r][c] = 0ull;
    mac88p(Xs, Ws2, 64, qo, oo, acc2);
    float4 bs0 = *(const float4*)(b2 + oo*8);
    float4 bs1 = *(const float4*)(b2 + oo*8 + 4);
    float bias[8] = {bs0.x,bs0.y,bs0.z,bs0.w,bs1.x,bs1.y,bs1.z,bs1.w};
    float sc1[8], sh1[8];
    #pragma unroll
    for (int c = 0; c < 8; c++) { sc1[c] = ssc0[oo*8+c]; sh1[c] = ssh0[oo*8+c]; }
    #pragma unroll
    for (int r = 0; r < 4; r++) {
        int p0 = pbase + 2*(qo + 32*r);
        const float* t1p = g_t1 + (size_t)p0*DD + oo*8;
        float4 a0 = *(const float4*)t1p;
        float4 a1 = *(const float4*)(t1p + 4);
        float4 b0 = *(const float4*)(t1p + DD);
        float4 b1v = *(const float4*)(t1p + DD + 4);
        float t10[8] = {a0.x,a0.y,a0.z,a0.w,a1.x,a1.y,a1.z,a1.w};
        float t11[8] = {b0.x,b0.y,b0.z,b0.w,b1v.x,b1v.y,b1v.z,b1v.w};
        int g = 2*r + (qo >> 4);
        int sg = blockIdx.x*8 + g;
        int ob = sg >> 10, os = sg & 1023;
        #pragma unroll
        for (int c = 0; c < 8; c++) {
            unsigned u0, u1; UNPACK2(u0, u1, acc2[r][c]);
            float res0 = fmaxf(sc1[c]*t10[c] + sh1[c], 0.f);
            float res1 = fmaxf(sc1[c]*t11[c] + sh1[c], 0.f);
            float v0 = fmaxf(__uint_as_float(u0) + bias[c] + res0, 0.f);
            float v1 = fmaxf(__uint_as_float(u1) + bias[c] + res1, 0.f);
            float mm = fmaxf(v0, v1);
            mm = fmaxf(mm, __shfl_xor_sync(0xffffffffu, mm, 8));
            mm = fmaxf(mm, __shfl_xor_sync(0xffffffffu, mm, 4));
            mm = fmaxf(mm, __shfl_xor_sync(0xffffffffu, mm, 2));
            mm = fmaxf(mm, __shfl_xor_sync(0xffffffffu, mm, 1));
            if ((qo & 15) == 0)
                outF[(size_t)(ob*DD + oo*8 + c)*SS + os] = mm;
        }
    }
}

extern "C" void kernel_launch(void* const* d_in, const int* in_sizes, int n_in,
                              void* d_out, int out_size) {
    const float* xyz   = (const float*)d_in[0];
    const float* feat  = (const float*)d_in[1];
    const float* alpha = (const float*)d_in[2];
    const float* beta  = (const float*)d_in[3];
    const float* w_tr  = (const float*)d_in[4];
    const float* b_tr  = (const float*)d_in[5];
    const float* g_tr  = (const float*)d_in[6];
    const float* be_tr = (const float*)d_in[7];
    const float* w1    = (const float*)d_in[8];
    const float* b1    = (const float*)d_in[9];
    const float* g1    = (const float*)d_in[10];
    const float* be1   = (const float*)d_in[11];
    const float* w2    = (const float*)d_in[12];
    const float* b2    = (const float*)d_in[13];
    float* out = (float*)d_out;
    float* outF = out + BB*3*SS;

    const int SM1 = (131*256 + 131*128) * 4;
    const int SM2 = (64*256 + 64*128) * 4;

    static cudaStream_t s2 = nullptr;
    static cudaEvent_t evA = nullptr, evB = nullptr;
    if (!s2) {
        cudaFuncSetAttribute(k_fps,  cudaFuncAttributeMaxDynamicSharedMemorySize, 3*NN*4);
        cudaFuncSetAttribute(k_conv1, cudaFuncAttributeMaxDynamicSharedMemorySize, SM1);
        cudaFuncSetAttribute(k_conv2, cudaFuncAttributeMaxDynamicSharedMemorySize, SM2);
        cudaFuncSetAttribute(k_conv3, cudaFuncAttributeMaxDynamicSharedMemorySize, SM2);
        cudaStreamCreateWithFlags(&s2, cudaStreamNonBlocking);
        cudaEventCreateWithFlags(&evA, cudaEventDisableTiming);
        cudaEventCreateWithFlags(&evB, cudaEventDisableTiming);
    }

    k_txyz<<<BB*NN/256, 256>>>(xyz);
    cudaEventRecord(evA, 0);
    cudaStreamWaitEvent(s2, evA, 0);
    {
        dim3 g(NN/32, DD/32, BB), t(32, 8);
        k_tfeat<<<g, t, 0, s2>>>(feat);   // overlaps with k_fps
    }
    cudaEventRecord(evB, s2);
    k_fps<<<BB, 512, 3*NN*4>>>(out);
    cudaStreamWaitEvent(0, evB, 0);
    k_knn<<<BB*SS, 128>>>();
    k_stdfin<<<1, 32>>>();
    k_conv1<<<PP/256, 256, SM1>>>(alpha, beta, w_tr, b_tr);
    k_bnfin<<<1, 64>>>(0, g_tr, be_tr);
    k_conv2<<<PP/256, 256, SM2>>>(w1, b1);
    k_bnfin<<<1, 64>>>(1, g1, be1);
    k_conv3<<<PP/256, 256, SM2>>>(w2, b2, outF);
}